// round 9
// baseline (speedup 1.0000x reference)
#include <cuda_runtime.h>

#define NN 50000
#define FF 64
#define EE 800000
#define SCAN_BLOCKS ((NN + 255) / 256)   // 196
#define EX_CAP 128

// Scratch (static __device__ — zero-initialized at load; kernels restore their
// scratch to zero each execution so graph replays are deterministic)
__device__ float        g_q[(size_t)NN * 128];    // [N][h*64+f]
__device__ float        g_k[(size_t)NN * 128];
__device__ int          g_hist[NN];
__device__ int          g_start[NN + 1];
__device__ unsigned int g_state[SCAN_BLOCKS];     // lookback: (sum<<2)|status
__device__ int          g_cursor[NN];
__device__ int2         g_sedge[EE];              // (col, orig edge id) row-sorted
__device__ float        g_ex2[(size_t)EE * 2];    // fallback exp storage (deg > EX_CAP)

// f32x2 packed-math helpers (Blackwell FFMA2 path — only reachable via PTX)
#define FMA_F32X2(d, a, b, c) \
    asm("fma.rn.f32x2 %0, %1, %2, %3;" : "=l"(d) : "l"(a), "l"(b), "l"(c))
#define ADD_F32X2(d, a, b) \
    asm("add.rn.f32x2 %0, %1, %2;" : "=l"(d) : "l"(a), "l"(b))
#define PACK_F32X2(d, lo, hi) \
    asm("mov.b64 %0, {%1, %2};" : "=l"(d) : "f"(lo), "f"(hi))
#define UNPACK_F32X2(lo, hi, s) \
    asm("mov.b64 {%0, %1}, %2;" : "=f"(lo), "=f"(hi) : "l"(s))

// ---------------- counting sort of edges by row ----------------

__global__ void hist_kernel(const int4* __restrict__ row4) {
    int i = blockIdx.x * blockDim.x + threadIdx.x;
    if (i < EE / 4) {
        int4 r = __ldg(row4 + i);
        atomicAdd(&g_hist[r.x], 1);
        atomicAdd(&g_hist[r.y], 1);
        atomicAdd(&g_hist[r.z], 1);
        atomicAdd(&g_hist[r.w], 1);
    }
}

// Single-pass exclusive scan with decoupled lookback. Packed state word
// (sum<<2 | status), status: 0=invalid 1=aggregate 2=inclusive-prefix; sums
// <= 800000 fit in 30 bits so the word is self-contained (no extra fencing).
// All 196 blocks are co-resident (256 thr, tiny smem) -> spin is safe.
// Also resets g_hist; g_state is reset by scatter_kernel (after all readers).
__global__ void scan_lb_kernel() {
    __shared__ int sh[256];
    __shared__ int s_exc;
    const int t = threadIdx.x;
    const int bid = blockIdx.x;
    const int i = bid * 256 + t;
    int v = 0;
    if (i < NN) { v = g_hist[i]; g_hist[i] = 0; }
    sh[t] = v;
    __syncthreads();
#pragma unroll
    for (int off = 1; off < 256; off <<= 1) {
        int u = (t >= off) ? sh[t - off] : 0;
        __syncthreads();
        sh[t] += u;
        __syncthreads();
    }
    const int blockAgg = sh[255];

    if (t == 0) {
        if (bid == 0) {
            atomicExch(&g_state[0], ((unsigned)blockAgg << 2) | 2u);
            s_exc = 0;
        } else {
            atomicExch(&g_state[bid], ((unsigned)blockAgg << 2) | 1u);
            int exc = 0;
            int p = bid - 1;
            while (true) {
                unsigned st;
                do { st = atomicOr(&g_state[p], 0u); } while ((st & 3u) == 0u);
                exc += (int)(st >> 2);
                if ((st & 3u) == 2u) break;
                p--;
            }
            atomicExch(&g_state[bid], ((unsigned)(exc + blockAgg) << 2) | 2u);
            s_exc = exc;
        }
    }
    __syncthreads();
    const int base = s_exc;
    if (i < NN) {
        int s = sh[t] - v + base;   // exclusive
        g_start[i] = s;
        g_cursor[i] = s;
    }
    if (i == 0) g_start[NN] = EE;
}

__global__ void scatter_kernel(const int* __restrict__ row, const int* __restrict__ col) {
    // reset lookback state for the next graph replay (no reader of g_state here)
    if (blockIdx.x == 0 && threadIdx.x < SCAN_BLOCKS) g_state[threadIdx.x] = 0u;
    int e = blockIdx.x * blockDim.x + threadIdx.x;
    if (e >= EE) return;
    int r = row[e];
    int pos = atomicAdd(&g_cursor[r], 1);
    g_sedge[pos] = make_int2(col[e], e);
}

// ---------------- QK projection GEMM (K-paired FFMA2, low regs) ----------------
__global__ void __launch_bounds__(256) gemm_qk_kernel(const float* __restrict__ x,
                                                      const float* __restrict__ W,
                                                      const float* __restrict__ b) {
    __shared__ float xs[64 * 64];    // 16KB
    const int c  = threadIdx.x;      // output column 0..255
    const int n0 = blockIdx.x * 64;

#pragma unroll
    for (int i = 0; i < 4; i++) {
        int lin = c + i * 256;               // float4 index
        int r = lin >> 4, k4 = lin & 15;
        int n = n0 + r;
        float4 v = make_float4(0.f, 0.f, 0.f, 0.f);
        if (n < NN) v = __ldg((const float4*)x + (size_t)n * 16 + k4);
        *((float4*)&xs[r * 64 + k4 * 4]) = v;
    }

    unsigned long long wp2[32];
#pragma unroll
    for (int j = 0; j < 32; j++) {
        float w0 = __ldg(W + (2 * j) * 256 + c);
        float w1 = __ldg(W + (2 * j + 1) * 256 + c);
        PACK_F32X2(wp2[j], w0, w1);
    }
    const float bc = __ldg(b + c);

    __syncthreads();

    const int h = c >> 7;
    const int sflag = (c >> 6) & 1;          // 0 -> q table, 1 -> k table
    const int f = c & 63;
    float* outbase = sflag ? g_k : g_q;

    const int rows = (NN - n0 < 64) ? (NN - n0) : 64;
    for (int r = 0; r < rows; r++) {
        unsigned long long acc0, acc1;
        PACK_F32X2(acc0, bc, 0.0f);
        PACK_F32X2(acc1, 0.0f, 0.0f);
        const ulonglong2* xr = (const ulonglong2*)&xs[r * 64];
#pragma unroll
        for (int j = 0; j < 16; j++) {
            ulonglong2 xv = xr[j];
            FMA_F32X2(acc0, xv.x, wp2[2 * j], acc0);
            FMA_F32X2(acc1, xv.y, wp2[2 * j + 1], acc1);
        }
        unsigned long long acc;
        ADD_F32X2(acc, acc0, acc1);
        float lo, hi;
        UNPACK_F32X2(lo, hi, acc);
        outbase[(size_t)(n0 + r) * 128 + h * 64 + f] = lo + hi;
    }
}

// ---------------- fused edge scores + softmax + output ----------------
// One warp per row. The row's sedge entries are staged into smem once
// (coalesced), removing the per-iteration global dependency from the k-load
// address chain; the staged copy also serves the output permutation loop.
__global__ void __launch_bounds__(256) edge_row_kernel(float* __restrict__ out) {
    __shared__ float2 exs[8][EX_CAP + 4];
    __shared__ int2   sse[8][EX_CAP];
    const int warp = threadIdx.x >> 5;
    const int lane = threadIdx.x & 31;
    const int r = blockIdx.x * 8 + warp;
    if (r >= NN) return;

    const int s0 = g_start[r];
    const int s1 = g_start[r + 1];
    const int deg = s1 - s0;
    if (deg == 0) return;

    const float4 qv = *(const float4*)(g_q + (size_t)r * 128 + lane * 4);
    const float4* kp = (const float4*)g_k;
    const bool head_lane = ((lane & 15) == 0);
    const int h = lane >> 4;
    float d = 0.0f;

    if (deg <= EX_CAP) {
        for (int j = lane; j < deg; j += 32) sse[warp][j] = g_sedge[s0 + j];
        __syncwarp();

        int pos = 0;
        const int qend = deg & ~3;
        for (; pos < qend; pos += 4) {
            int c0 = sse[warp][pos].x,     c1 = sse[warp][pos + 1].x;
            int c2 = sse[warp][pos + 2].x, c3 = sse[warp][pos + 3].x;
            float4 k0 = __ldg(kp + c0 * 32 + lane);
            float4 k1 = __ldg(kp + c1 * 32 + lane);
            float4 k2 = __ldg(kp + c2 * 32 + lane);
            float4 k3 = __ldg(kp + c3 * 32 + lane);
            float p0 = qv.x * k0.x + qv.y * k0.y + qv.z * k0.z + qv.w * k0.w;
            float p1 = qv.x * k1.x + qv.y * k1.y + qv.z * k1.z + qv.w * k1.w;
            float p2 = qv.x * k2.x + qv.y * k2.y + qv.z * k2.z + qv.w * k2.w;
            float p3 = qv.x * k3.x + qv.y * k3.y + qv.z * k3.z + qv.w * k3.w;
#pragma unroll
            for (int off = 8; off >= 1; off >>= 1) {
                p0 += __shfl_xor_sync(0xffffffffu, p0, off);
                p1 += __shfl_xor_sync(0xffffffffu, p1, off);
                p2 += __shfl_xor_sync(0xffffffffu, p2, off);
                p3 += __shfl_xor_sync(0xffffffffu, p3, off);
            }
            if (head_lane) {
                float v0 = __expf(p0), v1 = __expf(p1);
                float v2 = __expf(p2), v3 = __expf(p3);
                ((float*)&exs[warp][pos + 0])[h] = v0;
                ((float*)&exs[warp][pos + 1])[h] = v1;
                ((float*)&exs[warp][pos + 2])[h] = v2;
                ((float*)&exs[warp][pos + 3])[h] = v3;
                d += (v0 + v1) + (v2 + v3);
            }
        }
        for (; pos < deg; pos++) {
            int c0 = sse[warp][pos].x;
            float4 k0 = __ldg(kp + c0 * 32 + lane);
            float p0 = qv.x * k0.x + qv.y * k0.y + qv.z * k0.z + qv.w * k0.w;
#pragma unroll
            for (int off = 8; off >= 1; off >>= 1)
                p0 += __shfl_xor_sync(0xffffffffu, p0, off);
            if (head_lane) {
                float v0 = __expf(p0);
                ((float*)&exs[warp][pos])[h] = v0;
                d += v0;
            }
        }
        float D0 = __shfl_sync(0xffffffffu, d, 0);
        float D1 = __shfl_sync(0xffffffffu, d, 16);
        float i0 = 0.5f / D0, i1 = 0.5f / D1;
        __syncwarp();
        for (int j = lane; j < deg; j += 32) {
            float2 e = exs[warp][j];
            out[sse[warp][j].y] = e.x * i0 + e.y * i1;
        }
    } else {
        // fallback (deg > 128; unreachable for this input)
        for (int posg = s0; posg < s1; posg++) {
            int2 e0 = g_sedge[posg];
            float4 k0 = __ldg(kp + e0.x * 32 + lane);
            float p0 = qv.x * k0.x + qv.y * k0.y + qv.z * k0.z + qv.w * k0.w;
#pragma unroll
            for (int off = 8; off >= 1; off >>= 1)
                p0 += __shfl_xor_sync(0xffffffffu, p0, off);
            if (head_lane) {
                float v0 = __expf(p0);
                g_ex2[2 * (size_t)posg + h] = v0;
                d += v0;
            }
        }
        float D0 = __shfl_sync(0xffffffffu, d, 0);
        float D1 = __shfl_sync(0xffffffffu, d, 16);
        float i0 = 0.5f / D0, i1 = 0.5f / D1;
        __syncwarp();
        for (int j = lane; j < deg; j += 32) {
            float2 e = *(const float2*)(g_ex2 + 2 * (size_t)(s0 + j));
            out[g_sedge[s0 + j].y] = e.x * i0 + e.y * i1;
        }
    }
}

extern "C" void kernel_launch(void* const* d_in, const int* in_sizes, int n_in,
                              void* d_out, int out_size) {
    const float* x    = (const float*)d_in[0];
    const float* W_qk = (const float*)d_in[1];
    const float* b_qk = (const float*)d_in[2];
    const int*   ei   = (const int*)d_in[3];   // [2, E] row-major
    const int* row = ei;
    const int* col = ei + EE;
    float* out = (float*)d_out;

    // Fork: GEMM on s2 waits only on the capture origin -> still overlaps the
    // entire sort chain. Launched 4th in code order (profiler captures #4).
    cudaStream_t s2;
    cudaEvent_t evFork, evJoin;
    cudaStreamCreateWithFlags(&s2, cudaStreamNonBlocking);
    cudaEventCreateWithFlags(&evFork, cudaEventDisableTiming);
    cudaEventCreateWithFlags(&evJoin, cudaEventDisableTiming);

    cudaEventRecord(evFork, 0);
    cudaStreamWaitEvent(s2, evFork, 0);

    hist_kernel<<<(EE / 4 + 255) / 256, 256>>>((const int4*)row);
    scan_lb_kernel<<<SCAN_BLOCKS, 256>>>();
    scatter_kernel<<<(EE + 255) / 256, 256>>>(row, col);

    gemm_qk_kernel<<<(NN + 63) / 64, 256, 0, s2>>>(x, W_qk, b_qk);
    cudaEventRecord(evJoin, s2);

    cudaStreamWaitEvent(0, evJoin, 0);
    edge_row_kernel<<<(NN + 7) / 8, 256>>>(out);
}

// round 10
// speedup vs baseline: 1.0011x; 1.0011x over previous
#include <cuda_runtime.h>

#define NN 50000
#define FF 64
#define EE 800000
#define SCAN_BLOCKS ((NN + 255) / 256)   // 196
#define EX_CAP 128
#define GEMM_SMEM (64 * 64 * 8 + 64 * 256 * 4)   // dup-x 32KB + W 64KB = 96KB

// Scratch (static __device__ — zero-initialized at load; kernels restore their
// scratch to zero each execution so graph replays are deterministic)
__device__ float        g_q[(size_t)NN * 128];    // [N][h*64+f]
__device__ float        g_k[(size_t)NN * 128];
__device__ int          g_hist[NN];
__device__ int          g_start[NN + 1];
__device__ unsigned int g_state[SCAN_BLOCKS];     // lookback: (sum<<2)|status
__device__ int          g_cursor[NN];
__device__ int2         g_sedge[EE];              // (col, orig edge id) row-sorted
__device__ float        g_ex2[(size_t)EE * 2];    // fallback exp storage (deg > EX_CAP)

// f32x2 packed-math helpers (Blackwell FFMA2 path — only reachable via PTX)
#define FMA_F32X2(d, a, b, c) \
    asm("fma.rn.f32x2 %0, %1, %2, %3;" : "=l"(d) : "l"(a), "l"(b), "l"(c))
#define PACK_F32X2(d, lo, hi) \
    asm("mov.b64 %0, {%1, %2};" : "=l"(d) : "f"(lo), "f"(hi))
#define UNPACK_F32X2(lo, hi, s) \
    asm("mov.b64 {%0, %1}, %2;" : "=f"(lo), "=f"(hi) : "l"(s))

// ---------------- counting sort of edges by row ----------------

__global__ void hist_kernel(const int4* __restrict__ row4) {
    int i = blockIdx.x * blockDim.x + threadIdx.x;
    if (i < EE / 4) {
        int4 r = __ldg(row4 + i);
        atomicAdd(&g_hist[r.x], 1);
        atomicAdd(&g_hist[r.y], 1);
        atomicAdd(&g_hist[r.z], 1);
        atomicAdd(&g_hist[r.w], 1);
    }
}

// Single-pass exclusive scan with decoupled lookback (packed state word).
// Also resets g_hist; g_state is reset by scatter_kernel (after all readers).
__global__ void scan_lb_kernel() {
    __shared__ int sh[256];
    __shared__ int s_exc;
    const int t = threadIdx.x;
    const int bid = blockIdx.x;
    const int i = bid * 256 + t;
    int v = 0;
    if (i < NN) { v = g_hist[i]; g_hist[i] = 0; }
    sh[t] = v;
    __syncthreads();
#pragma unroll
    for (int off = 1; off < 256; off <<= 1) {
        int u = (t >= off) ? sh[t - off] : 0;
        __syncthreads();
        sh[t] += u;
        __syncthreads();
    }
    const int blockAgg = sh[255];

    if (t == 0) {
        if (bid == 0) {
            atomicExch(&g_state[0], ((unsigned)blockAgg << 2) | 2u);
            s_exc = 0;
        } else {
            atomicExch(&g_state[bid], ((unsigned)blockAgg << 2) | 1u);
            int exc = 0;
            int p = bid - 1;
            while (true) {
                unsigned st;
                do { st = atomicOr(&g_state[p], 0u); } while ((st & 3u) == 0u);
                exc += (int)(st >> 2);
                if ((st & 3u) == 2u) break;
                p--;
            }
            atomicExch(&g_state[bid], ((unsigned)(exc + blockAgg) << 2) | 2u);
            s_exc = exc;
        }
    }
    __syncthreads();
    const int base = s_exc;
    if (i < NN) {
        int s = sh[t] - v + base;   // exclusive
        g_start[i] = s;
        g_cursor[i] = s;
    }
    if (i == 0) g_start[NN] = EE;
}

__global__ void scatter_kernel(const int* __restrict__ row, const int* __restrict__ col) {
    if (blockIdx.x == 0 && threadIdx.x < SCAN_BLOCKS) g_state[threadIdx.x] = 0u;
    int e = blockIdx.x * blockDim.x + threadIdx.x;
    if (e >= EE) return;
    int r = row[e];
    int pos = atomicAdd(&g_cursor[r], 1);
    g_sedge[pos] = make_int2(col[e], e);
}

// ---------------- QK projection GEMM (register-tiled FFMA2) ----------------
// Block: 64 rows x 256 cols. Thread: 8 rows x 8 cols (64 fp32 accs as 32 f32x2).
// Per k-pair: 8 dup-x LDS.128 + 4 W LDS.128 feed 64 FMA2 (8:1 fma:lds vs the
// old 2:1 that saturated L1 at fma=36%). Dynamic smem: dup-x 32KB + W 64KB.
__global__ void __launch_bounds__(256) gemm_qk_kernel(const float* __restrict__ x,
                                                      const float* __restrict__ W,
                                                      const float* __restrict__ b) {
    extern __shared__ float smem[];
    float2* xs = (float2*)smem;              // [64 rows][64 k] dup (v,v), 32KB
    float*  ws = smem + 64 * 64 * 2;         // [64 k][256 c], 64KB
    const int tid = threadIdx.x;
    const int n0 = blockIdx.x * 64;

    // stage x (dup pairs): 1024 float4, 4 per thread, coalesced
#pragma unroll
    for (int i = 0; i < 4; i++) {
        int lin = tid + i * 256;             // float4 index
        int r = lin >> 4, k4 = lin & 15;
        int n = n0 + r;
        float4 v = make_float4(0.f, 0.f, 0.f, 0.f);
        if (n < NN) v = __ldg((const float4*)x + (size_t)n * 16 + k4);
        float2* dst = &xs[r * 64 + k4 * 4];
        dst[0] = make_float2(v.x, v.x);
        dst[1] = make_float2(v.y, v.y);
        dst[2] = make_float2(v.z, v.z);
        dst[3] = make_float2(v.w, v.w);
    }
    // stage W: 4096 float4, 16 per thread, coalesced
#pragma unroll
    for (int i = 0; i < 16; i++) {
        int lin = tid + i * 256;
        ((float4*)ws)[lin] = __ldg((const float4*)W + lin);
    }
    __syncthreads();

    const int tx = tid & 31;                 // col tile: cols c0..c0+7
    const int ty = tid >> 5;                 // row tile: rows ty*8..+7
    const int c0 = tx * 8;

    unsigned long long acc[8][4];
    {
        float4 b0 = __ldg((const float4*)(b + c0));
        float4 b1 = __ldg((const float4*)(b + c0 + 4));
        unsigned long long bp[4];
        PACK_F32X2(bp[0], b0.x, b0.y);
        PACK_F32X2(bp[1], b0.z, b0.w);
        PACK_F32X2(bp[2], b1.x, b1.y);
        PACK_F32X2(bp[3], b1.z, b1.w);
#pragma unroll
        for (int r = 0; r < 8; r++)
#pragma unroll
            for (int cp = 0; cp < 4; cp++) acc[r][cp] = (r == 0) ? bp[cp] : 0ull;
    }

#pragma unroll 4
    for (int kp = 0; kp < 32; kp++) {
        const ulonglong2* wr0 = (const ulonglong2*)&ws[(2 * kp) * 256 + c0];
        const ulonglong2* wr1 = (const ulonglong2*)&ws[(2 * kp + 1) * 256 + c0];
        ulonglong2 wa = wr0[0], wb = wr0[1];   // k0: col pairs 0-1, 2-3
        ulonglong2 wc = wr1[0], wd = wr1[1];   // k1
#pragma unroll
        for (int r = 0; r < 8; r++) {
            ulonglong2 a = *(const ulonglong2*)&xs[(ty * 8 + r) * 64 + 2 * kp];
            FMA_F32X2(acc[r][0], a.x, wa.x, acc[r][0]);
            FMA_F32X2(acc[r][1], a.x, wa.y, acc[r][1]);
            FMA_F32X2(acc[r][2], a.x, wb.x, acc[r][2]);
            FMA_F32X2(acc[r][3], a.x, wb.y, acc[r][3]);
            FMA_F32X2(acc[r][0], a.y, wc.x, acc[r][0]);
            FMA_F32X2(acc[r][1], a.y, wc.y, acc[r][1]);
            FMA_F32X2(acc[r][2], a.y, wd.x, acc[r][2]);
            FMA_F32X2(acc[r][3], a.y, wd.y, acc[r][3]);
        }
    }

    const int h = c0 >> 7;
    const int sflag = (c0 >> 6) & 1;         // 0 -> q table, 1 -> k table
    const int f = c0 & 63;
    float* outbase = sflag ? g_k : g_q;

#pragma unroll
    for (int r = 0; r < 8; r++) {
        int n = n0 + ty * 8 + r;
        if (n >= NN) break;
        float o[8];
        UNPACK_F32X2(o[0], o[1], acc[r][0]);
        UNPACK_F32X2(o[2], o[3], acc[r][1]);
        UNPACK_F32X2(o[4], o[5], acc[r][2]);
        UNPACK_F32X2(o[6], o[7], acc[r][3]);
        float* dst = outbase + (size_t)n * 128 + h * 64 + f;
        *(float4*)dst       = make_float4(o[0], o[1], o[2], o[3]);
        *(float4*)(dst + 4) = make_float4(o[4], o[5], o[6], o[7]);
    }
}

// ---------------- fused edge scores + softmax + output (R9) ----------------
__global__ void __launch_bounds__(256) edge_row_kernel(float* __restrict__ out) {
    __shared__ float2 exs[8][EX_CAP + 4];
    __shared__ int2   sse[8][EX_CAP];
    const int warp = threadIdx.x >> 5;
    const int lane = threadIdx.x & 31;
    const int r = blockIdx.x * 8 + warp;
    if (r >= NN) return;

    const int s0 = g_start[r];
    const int s1 = g_start[r + 1];
    const int deg = s1 - s0;
    if (deg == 0) return;

    const float4 qv = *(const float4*)(g_q + (size_t)r * 128 + lane * 4);
    const float4* kp = (const float4*)g_k;
    const bool head_lane = ((lane & 15) == 0);
    const int h = lane >> 4;
    float d = 0.0f;

    if (deg <= EX_CAP) {
        for (int j = lane; j < deg; j += 32) sse[warp][j] = g_sedge[s0 + j];
        __syncwarp();

        int pos = 0;
        const int qend = deg & ~3;
        for (; pos < qend; pos += 4) {
            int c0 = sse[warp][pos].x,     c1 = sse[warp][pos + 1].x;
            int c2 = sse[warp][pos + 2].x, c3 = sse[warp][pos + 3].x;
            float4 k0 = __ldg(kp + c0 * 32 + lane);
            float4 k1 = __ldg(kp + c1 * 32 + lane);
            float4 k2 = __ldg(kp + c2 * 32 + lane);
            float4 k3 = __ldg(kp + c3 * 32 + lane);
            float p0 = qv.x * k0.x + qv.y * k0.y + qv.z * k0.z + qv.w * k0.w;
            float p1 = qv.x * k1.x + qv.y * k1.y + qv.z * k1.z + qv.w * k1.w;
            float p2 = qv.x * k2.x + qv.y * k2.y + qv.z * k2.z + qv.w * k2.w;
            float p3 = qv.x * k3.x + qv.y * k3.y + qv.z * k3.z + qv.w * k3.w;
#pragma unroll
            for (int off = 8; off >= 1; off >>= 1) {
                p0 += __shfl_xor_sync(0xffffffffu, p0, off);
                p1 += __shfl_xor_sync(0xffffffffu, p1, off);
                p2 += __shfl_xor_sync(0xffffffffu, p2, off);
                p3 += __shfl_xor_sync(0xffffffffu, p3, off);
            }
            if (head_lane) {
                float v0 = __expf(p0), v1 = __expf(p1);
                float v2 = __expf(p2), v3 = __expf(p3);
                ((float*)&exs[warp][pos + 0])[h] = v0;
                ((float*)&exs[warp][pos + 1])[h] = v1;
                ((float*)&exs[warp][pos + 2])[h] = v2;
                ((float*)&exs[warp][pos + 3])[h] = v3;
                d += (v0 + v1) + (v2 + v3);
            }
        }
        for (; pos < deg; pos++) {
            int c0 = sse[warp][pos].x;
            float4 k0 = __ldg(kp + c0 * 32 + lane);
            float p0 = qv.x * k0.x + qv.y * k0.y + qv.z * k0.z + qv.w * k0.w;
#pragma unroll
            for (int off = 8; off >= 1; off >>= 1)
                p0 += __shfl_xor_sync(0xffffffffu, p0, off);
            if (head_lane) {
                float v0 = __expf(p0);
                ((float*)&exs[warp][pos])[h] = v0;
                d += v0;
            }
        }
        float D0 = __shfl_sync(0xffffffffu, d, 0);
        float D1 = __shfl_sync(0xffffffffu, d, 16);
        float i0 = 0.5f / D0, i1 = 0.5f / D1;
        __syncwarp();
        for (int j = lane; j < deg; j += 32) {
            float2 e = exs[warp][j];
            out[sse[warp][j].y] = e.x * i0 + e.y * i1;
        }
    } else {
        // fallback (deg > 128; unreachable for this input)
        for (int posg = s0; posg < s1; posg++) {
            int2 e0 = g_sedge[posg];
            float4 k0 = __ldg(kp + e0.x * 32 + lane);
            float p0 = qv.x * k0.x + qv.y * k0.y + qv.z * k0.z + qv.w * k0.w;
#pragma unroll
            for (int off = 8; off >= 1; off >>= 1)
                p0 += __shfl_xor_sync(0xffffffffu, p0, off);
            if (head_lane) {
                float v0 = __expf(p0);
                g_ex2[2 * (size_t)posg + h] = v0;
                d += v0;
            }
        }
        float D0 = __shfl_sync(0xffffffffu, d, 0);
        float D1 = __shfl_sync(0xffffffffu, d, 16);
        float i0 = 0.5f / D0, i1 = 0.5f / D1;
        __syncwarp();
        for (int j = lane; j < deg; j += 32) {
            float2 e = *(const float2*)(g_ex2 + 2 * (size_t)(s0 + j));
            out[g_sedge[s0 + j].y] = e.x * i0 + e.y * i1;
        }
    }
}

extern "C" void kernel_launch(void* const* d_in, const int* in_sizes, int n_in,
                              void* d_out, int out_size) {
    const float* x    = (const float*)d_in[0];
    const float* W_qk = (const float*)d_in[1];
    const float* b_qk = (const float*)d_in[2];
    const int*   ei   = (const int*)d_in[3];   // [2, E] row-major
    const int* row = ei;
    const int* col = ei + EE;
    float* out = (float*)d_out;

    // Opt-in to 96KB dynamic smem for the gemm (attribute set, not an alloc).
    cudaFuncSetAttribute(gemm_qk_kernel,
                         cudaFuncAttributeMaxDynamicSharedMemorySize, GEMM_SMEM);

    // Fork: GEMM on s2 overlaps the sort chain in the captured graph.
    cudaStream_t s2;
    cudaEvent_t evFork, evJoin;
    cudaStreamCreateWithFlags(&s2, cudaStreamNonBlocking);
    cudaEventCreateWithFlags(&evFork, cudaEventDisableTiming);
    cudaEventCreateWithFlags(&evJoin, cudaEventDisableTiming);

    cudaEventRecord(evFork, 0);
    cudaStreamWaitEvent(s2, evFork, 0);

    hist_kernel<<<(EE / 4 + 255) / 256, 256>>>((const int4*)row);
    scan_lb_kernel<<<SCAN_BLOCKS, 256>>>();
    scatter_kernel<<<(EE + 255) / 256, 256>>>(row, col);

    gemm_qk_kernel<<<(NN + 63) / 64, 256, GEMM_SMEM, s2>>>(x, W_qk, b_qk);
    cudaEventRecord(evJoin, s2);

    cudaStreamWaitEvent(0, evJoin, 0);
    edge_row_kernel<<<(NN + 7) / 8, 256>>>(out);
}

// round 11
// speedup vs baseline: 1.0570x; 1.0558x over previous
#include <cuda_runtime.h>
#include <cuda_fp16.h>
#include <cstdint>

#define NN 50000
#define FF 64
#define EE 800000
#define SCAN_BLOCKS ((NN + 255) / 256)   // 196
#define EX_CAP 128
// gemm smem: xs_h/xs_l [128][72] half + ws_h/ws_l [256][72] half (transposed W)
#define XS_BYTES (128 * 72 * 2)          // 18432
#define WS_BYTES (256 * 72 * 2)          // 36864
#define GEMM_SMEM (2 * XS_BYTES + 2 * WS_BYTES)   // 110592

// Scratch (static __device__ — zero-initialized at load; kernels restore their
// scratch to zero each execution so graph replays are deterministic)
__device__ float        g_q[(size_t)NN * 128];    // [N][h*64+f]
__device__ float        g_k[(size_t)NN * 128];
__device__ int          g_hist[NN];
__device__ int          g_start[NN + 1];
__device__ unsigned int g_state[SCAN_BLOCKS];     // lookback: (sum<<2)|status
__device__ int          g_cursor[NN];
__device__ int2         g_sedge[EE];              // (col, orig edge id) row-sorted
__device__ float        g_ex2[(size_t)EE * 2];    // fallback exp storage (deg > EX_CAP)

#define MMA16816(d, a0, a1, a2, a3, b0, b1) \
    asm volatile("mma.sync.aligned.m16n8k16.row.col.f32.f16.f16.f32 " \
        "{%0,%1,%2,%3}, {%4,%5,%6,%7}, {%8,%9}, {%0,%1,%2,%3};" \
        : "+f"((d)[0]), "+f"((d)[1]), "+f"((d)[2]), "+f"((d)[3]) \
        : "r"(a0), "r"(a1), "r"(a2), "r"(a3), "r"(b0), "r"(b1))

// ---------------- counting sort of edges by row ----------------

__global__ void hist_kernel(const int4* __restrict__ row4) {
    int i = blockIdx.x * blockDim.x + threadIdx.x;
    if (i < EE / 4) {
        int4 r = __ldg(row4 + i);
        atomicAdd(&g_hist[r.x], 1);
        atomicAdd(&g_hist[r.y], 1);
        atomicAdd(&g_hist[r.z], 1);
        atomicAdd(&g_hist[r.w], 1);
    }
}

// Single-pass exclusive scan with decoupled lookback (packed state word).
// Also resets g_hist; g_state is reset by scatter_kernel (after all readers).
__global__ void scan_lb_kernel() {
    __shared__ int sh[256];
    __shared__ int s_exc;
    const int t = threadIdx.x;
    const int bid = blockIdx.x;
    const int i = bid * 256 + t;
    int v = 0;
    if (i < NN) { v = g_hist[i]; g_hist[i] = 0; }
    sh[t] = v;
    __syncthreads();
#pragma unroll
    for (int off = 1; off < 256; off <<= 1) {
        int u = (t >= off) ? sh[t - off] : 0;
        __syncthreads();
        sh[t] += u;
        __syncthreads();
    }
    const int blockAgg = sh[255];

    if (t == 0) {
        if (bid == 0) {
            atomicExch(&g_state[0], ((unsigned)blockAgg << 2) | 2u);
            s_exc = 0;
        } else {
            atomicExch(&g_state[bid], ((unsigned)blockAgg << 2) | 1u);
            int exc = 0;
            int p = bid - 1;
            while (true) {
                unsigned st;
                do { st = atomicOr(&g_state[p], 0u); } while ((st & 3u) == 0u);
                exc += (int)(st >> 2);
                if ((st & 3u) == 2u) break;
                p--;
            }
            atomicExch(&g_state[bid], ((unsigned)(exc + blockAgg) << 2) | 2u);
            s_exc = exc;
        }
    }
    __syncthreads();
    const int base = s_exc;
    if (i < NN) {
        int s = sh[t] - v + base;   // exclusive
        g_start[i] = s;
        g_cursor[i] = s;
    }
    if (i == 0) g_start[NN] = EE;
}

__global__ void scatter_kernel(const int* __restrict__ row, const int* __restrict__ col) {
    if (blockIdx.x == 0 && threadIdx.x < SCAN_BLOCKS) g_state[threadIdx.x] = 0u;
    int e = blockIdx.x * blockDim.x + threadIdx.x;
    if (e >= EE) return;
    int r = row[e];
    int pos = atomicAdd(&g_cursor[r], 1);
    g_sedge[pos] = make_int2(col[e], e);
}

// ---------------- QK projection GEMM (tensor cores, fp16 split) ----------------
// D = xhi*Whi + xhi*Wlo + xlo*Whi (fp16 operands, fp32 acc): dropped xlo*Wlo
// term is ~2^-22 relative. Block: 128 rows x 256 cols, 512 thr = 16 warps in
// 8(M) x 2(N); warp = m16 x n128 (16 n8-tiles). Operands pre-split into padded
// smem (72-half rows -> conflict-free u32 fragment loads).
__global__ void __launch_bounds__(512) gemm_qk_kernel(const float* __restrict__ x,
                                                      const float* __restrict__ W,
                                                      const float* __restrict__ b) {
    extern __shared__ char sm_raw[];
    __half* xs_h = (__half*)sm_raw;                       // [128][72]
    __half* xs_l = (__half*)(sm_raw + XS_BYTES);
    __half* ws_h = (__half*)(sm_raw + 2 * XS_BYTES);      // [256][72] = W^T
    __half* ws_l = (__half*)(sm_raw + 2 * XS_BYTES + WS_BYTES);
    const int tid = threadIdx.x;
    const int n0 = blockIdx.x * 128;

    // stage x -> hi/lo halves (2048 float4, 4 per thread)
#pragma unroll
    for (int i = 0; i < 4; i++) {
        int lin = tid + i * 512;
        int r = lin >> 4, k4 = lin & 15;
        int n = n0 + r;
        float4 v = make_float4(0.f, 0.f, 0.f, 0.f);
        if (n < NN) v = __ldg((const float4*)x + (size_t)n * 16 + k4);
        float cc[4] = {v.x, v.y, v.z, v.w};
#pragma unroll
        for (int j = 0; j < 4; j++) {
            int k = k4 * 4 + j;
            __half h = __float2half_rn(cc[j]);
            float lo = cc[j] - __half2float(h);
            xs_h[r * 72 + k] = h;
            xs_l[r * 72 + k] = __float2half_rn(lo);
        }
    }
    // stage W transposed -> hi/lo (4096 float4, 8 per thread)
#pragma unroll
    for (int i = 0; i < 8; i++) {
        int lin = tid + i * 512;
        int k = lin >> 6, nq = lin & 63;
        float4 v = __ldg((const float4*)W + lin);
        float cc[4] = {v.x, v.y, v.z, v.w};
#pragma unroll
        for (int j = 0; j < 4; j++) {
            int n = nq * 4 + j;
            __half h = __float2half_rn(cc[j]);
            float lo = cc[j] - __half2float(h);
            ws_h[n * 72 + k] = h;
            ws_l[n * 72 + k] = __float2half_rn(lo);
        }
    }
    __syncthreads();

    const int warp = tid >> 5, lane = tid & 31;
    const int wm = warp >> 1, wn = warp & 1;
    const int g = lane >> 2, t = lane & 3;
    const int rowb = wm * 16;

    float acc[16][4];
#pragma unroll
    for (int nt = 0; nt < 16; nt++) {
        int col0 = wn * 128 + nt * 8 + 2 * t;
        float2 bb = *(const float2*)(b + col0);
        acc[nt][0] = bb.x; acc[nt][1] = bb.y;
        acc[nt][2] = bb.x; acc[nt][3] = bb.y;
    }

#pragma unroll
    for (int ks = 0; ks < 4; ks++) {
        const int ka = ks * 16 + 2 * t;
        const int ra = (rowb + g) * 72, rb = (rowb + g + 8) * 72;
        uint32_t ah0 = *(const uint32_t*)&xs_h[ra + ka];
        uint32_t ah1 = *(const uint32_t*)&xs_h[rb + ka];
        uint32_t ah2 = *(const uint32_t*)&xs_h[ra + ka + 8];
        uint32_t ah3 = *(const uint32_t*)&xs_h[rb + ka + 8];
        uint32_t al0 = *(const uint32_t*)&xs_l[ra + ka];
        uint32_t al1 = *(const uint32_t*)&xs_l[rb + ka];
        uint32_t al2 = *(const uint32_t*)&xs_l[ra + ka + 8];
        uint32_t al3 = *(const uint32_t*)&xs_l[rb + ka + 8];
#pragma unroll
        for (int nt = 0; nt < 16; nt++) {
            int n = (wn * 128 + nt * 8 + g) * 72;
            uint32_t bh0 = *(const uint32_t*)&ws_h[n + ka];
            uint32_t bh1 = *(const uint32_t*)&ws_h[n + ka + 8];
            uint32_t bl0 = *(const uint32_t*)&ws_l[n + ka];
            uint32_t bl1 = *(const uint32_t*)&ws_l[n + ka + 8];
            MMA16816(acc[nt], ah0, ah1, ah2, ah3, bh0, bh1);
            MMA16816(acc[nt], ah0, ah1, ah2, ah3, bl0, bl1);
            MMA16816(acc[nt], al0, al1, al2, al3, bh0, bh1);
        }
    }

    const int nr0 = n0 + rowb + g;
    const int nr1 = nr0 + 8;
#pragma unroll
    for (int nt = 0; nt < 16; nt++) {
        int cl = nt * 8 + 2 * t;                       // col within 128-range
        float* outbase = ((cl >> 6) & 1) ? g_k : g_q;  // q/k select
        int f = cl & 63;
        size_t off = (size_t)wn * 64 + f;
        if (nr0 < NN)
            *(float2*)(outbase + (size_t)nr0 * 128 + off) = make_float2(acc[nt][0], acc[nt][1]);
        if (nr1 < NN)
            *(float2*)(outbase + (size_t)nr1 * 128 + off) = make_float2(acc[nt][2], acc[nt][3]);
    }
}

// ---------------- fused edge scores + softmax + output ----------------
__global__ void __launch_bounds__(256) edge_row_kernel(float* __restrict__ out) {
    __shared__ float2 exs[8][EX_CAP + 4];
    __shared__ int2   sse[8][EX_CAP];
    const int warp = threadIdx.x >> 5;
    const int lane = threadIdx.x & 31;
    const int r = blockIdx.x * 8 + warp;
    if (r >= NN) return;

    const int s0 = g_start[r];
    const int s1 = g_start[r + 1];
    const int deg = s1 - s0;
    if (deg == 0) return;

    const float4 qv = *(const float4*)(g_q + (size_t)r * 128 + lane * 4);
    const float4* kp = (const float4*)g_k;
    const bool head_lane = ((lane & 15) == 0);
    const int h = lane >> 4;
    float d = 0.0f;

    if (deg <= EX_CAP) {
        for (int j = lane; j < deg; j += 32) sse[warp][j] = g_sedge[s0 + j];
        __syncwarp();

        int pos = 0;
        const int qend = deg & ~3;
        for (; pos < qend; pos += 4) {
            int c0 = sse[warp][pos].x,     c1 = sse[warp][pos + 1].x;
            int c2 = sse[warp][pos + 2].x, c3 = sse[warp][pos + 3].x;
            float4 k0 = __ldg(kp + c0 * 32 + lane);
            float4 k1 = __ldg(kp + c1 * 32 + lane);
            float4 k2 = __ldg(kp + c2 * 32 + lane);
            float4 k3 = __ldg(kp + c3 * 32 + lane);
            float p0 = qv.x * k0.x + qv.y * k0.y + qv.z * k0.z + qv.w * k0.w;
            float p1 = qv.x * k1.x + qv.y * k1.y + qv.z * k1.z + qv.w * k1.w;
            float p2 = qv.x * k2.x + qv.y * k2.y + qv.z * k2.z + qv.w * k2.w;
            float p3 = qv.x * k3.x + qv.y * k3.y + qv.z * k3.z + qv.w * k3.w;
#pragma unroll
            for (int off = 8; off >= 1; off >>= 1) {
                p0 += __shfl_xor_sync(0xffffffffu, p0, off);
                p1 += __shfl_xor_sync(0xffffffffu, p1, off);
                p2 += __shfl_xor_sync(0xffffffffu, p2, off);
                p3 += __shfl_xor_sync(0xffffffffu, p3, off);
            }
            if (head_lane) {
                float v0 = __expf(p0), v1 = __expf(p1);
                float v2 = __expf(p2), v3 = __expf(p3);
                ((float*)&exs[warp][pos + 0])[h] = v0;
                ((float*)&exs[warp][pos + 1])[h] = v1;
                ((float*)&exs[warp][pos + 2])[h] = v2;
                ((float*)&exs[warp][pos + 3])[h] = v3;
                d += (v0 + v1) + (v2 + v3);
            }
        }
        for (; pos < deg; pos++) {
            int c0 = sse[warp][pos].x;
            float4 k0 = __ldg(kp + c0 * 32 + lane);
            float p0 = qv.x * k0.x + qv.y * k0.y + qv.z * k0.z + qv.w * k0.w;
#pragma unroll
            for (int off = 8; off >= 1; off >>= 1)
                p0 += __shfl_xor_sync(0xffffffffu, p0, off);
            if (head_lane) {
                float v0 = __expf(p0);
                ((float*)&exs[warp][pos])[h] = v0;
                d += v0;
            }
        }
        float D0 = __shfl_sync(0xffffffffu, d, 0);
        float D1 = __shfl_sync(0xffffffffu, d, 16);
        float i0 = 0.5f / D0, i1 = 0.5f / D1;
        __syncwarp();
        for (int j = lane; j < deg; j += 32) {
            float2 e = exs[warp][j];
            out[sse[warp][j].y] = e.x * i0 + e.y * i1;
        }
    } else {
        // fallback (deg > 128; unreachable for this input)
        for (int posg = s0; posg < s1; posg++) {
            int2 e0 = g_sedge[posg];
            float4 k0 = __ldg(kp + e0.x * 32 + lane);
            float p0 = qv.x * k0.x + qv.y * k0.y + qv.z * k0.z + qv.w * k0.w;
#pragma unroll
            for (int off = 8; off >= 1; off >>= 1)
                p0 += __shfl_xor_sync(0xffffffffu, p0, off);
            if (head_lane) {
                float v0 = __expf(p0);
                g_ex2[2 * (size_t)posg + h] = v0;
                d += v0;
            }
        }
        float D0 = __shfl_sync(0xffffffffu, d, 0);
        float D1 = __shfl_sync(0xffffffffu, d, 16);
        float i0 = 0.5f / D0, i1 = 0.5f / D1;
        __syncwarp();
        for (int j = lane; j < deg; j += 32) {
            float2 e = *(const float2*)(g_ex2 + 2 * (size_t)(s0 + j));
            out[g_sedge[s0 + j].y] = e.x * i0 + e.y * i1;
        }
    }
}

extern "C" void kernel_launch(void* const* d_in, const int* in_sizes, int n_in,
                              void* d_out, int out_size) {
    const float* x    = (const float*)d_in[0];
    const float* W_qk = (const float*)d_in[1];
    const float* b_qk = (const float*)d_in[2];
    const int*   ei   = (const int*)d_in[3];   // [2, E] row-major
    const int* row = ei;
    const int* col = ei + EE;
    float* out = (float*)d_out;

    cudaFuncSetAttribute(gemm_qk_kernel,
                         cudaFuncAttributeMaxDynamicSharedMemorySize, GEMM_SMEM);

    // Fork: GEMM launched FIRST (submission-order priority) on s2, overlapping
    // the sort chain in the captured graph.
    cudaStream_t s2;
    cudaEvent_t evFork, evJoin;
    cudaStreamCreateWithFlags(&s2, cudaStreamNonBlocking);
    cudaEventCreateWithFlags(&evFork, cudaEventDisableTiming);
    cudaEventCreateWithFlags(&evJoin, cudaEventDisableTiming);

    cudaEventRecord(evFork, 0);
    cudaStreamWaitEvent(s2, evFork, 0);

    gemm_qk_kernel<<<(NN + 127) / 128, 512, GEMM_SMEM, s2>>>(x, W_qk, b_qk);
    cudaEventRecord(evJoin, s2);

    hist_kernel<<<(EE / 4 + 255) / 256, 256>>>((const int4*)row);
    scan_lb_kernel<<<SCAN_BLOCKS, 256>>>();
    scatter_kernel<<<(EE + 255) / 256, 256>>>(row, col);

    cudaStreamWaitEvent(0, evJoin, 0);
    edge_row_kernel<<<(NN + 7) / 8, 256>>>(out);
}